// round 8
// baseline (speedup 1.0000x reference)
#include <cuda_runtime.h>
#include <cuda_bf16.h>

#define N_NODES 50000
#define D_FEAT  128

// CSR row offsets into the sorted edge list. 50001 ints.
__device__ int g_offsets[N_NODES + 1];

// Kernel A: boundary-diff scatter. edge_src is sorted; thread e fills
// offsets[n] = e for all n in (edge_src[e-1], edge_src[e]].
__global__ void build_offsets_kernel(const int* __restrict__ edge_src, int n_edges) {
    int e = blockIdx.x * blockDim.x + threadIdx.x;
    if (e >= n_edges) return;
    int s1 = edge_src[e];
    int s0 = (e == 0) ? -1 : edge_src[e - 1];
    for (int n = s0 + 1; n <= s1; n++) g_offsets[n] = e;
    if (e == n_edges - 1) {
        for (int n = s1 + 1; n <= N_NODES; n++) g_offsets[n] = n_edges;
    }
}

// Kernel B: one warp per node, unroll-4 edges. Each row gather is split into
// 2x LDG.64 (lane reads float2 at row2[lane] and row2[lane+32]) so each load
// instruction spans 2 cache lines instead of 4 — fewer within-LDG L1tex
// wavefront replays than a single LDG.128 spanning 4 lines.
__global__ void __launch_bounds__(128)
graph_pool_kernel(const float2* __restrict__ x2,
                  const int* __restrict__ edge_dst,
                  float2* __restrict__ out2) {
    int warp_id = (blockIdx.x * blockDim.x + threadIdx.x) >> 5;
    int lane = threadIdx.x & 31;
    if (warp_id >= N_NODES) return;

    int beg = g_offsets[warp_id];
    int end = g_offsets[warp_id + 1];

    // self feature (row = 64 float2; this warp covers [lane] and [lane+32])
    float2 accA = x2[(size_t)warp_id * 64 + lane];
    float2 accB = x2[(size_t)warp_id * 64 + 32 + lane];

    int e = beg;
    for (; e + 4 <= end; e += 4) {
        int d0 = edge_dst[e + 0];
        int d1 = edge_dst[e + 1];
        int d2 = edge_dst[e + 2];
        int d3 = edge_dst[e + 3];
        float2 a0 = __ldg(&x2[(size_t)d0 * 64 + lane]);
        float2 b0 = __ldg(&x2[(size_t)d0 * 64 + 32 + lane]);
        float2 a1 = __ldg(&x2[(size_t)d1 * 64 + lane]);
        float2 b1 = __ldg(&x2[(size_t)d1 * 64 + 32 + lane]);
        float2 a2 = __ldg(&x2[(size_t)d2 * 64 + lane]);
        float2 b2 = __ldg(&x2[(size_t)d2 * 64 + 32 + lane]);
        float2 a3 = __ldg(&x2[(size_t)d3 * 64 + lane]);
        float2 b3 = __ldg(&x2[(size_t)d3 * 64 + 32 + lane]);
        accA.x += a0.x; accA.y += a0.y; accB.x += b0.x; accB.y += b0.y;
        accA.x += a1.x; accA.y += a1.y; accB.x += b1.x; accB.y += b1.y;
        accA.x += a2.x; accA.y += a2.y; accB.x += b2.x; accB.y += b2.y;
        accA.x += a3.x; accA.y += a3.y; accB.x += b3.x; accB.y += b3.y;
    }
    for (; e < end; e++) {
        int d = edge_dst[e];
        float2 a = __ldg(&x2[(size_t)d * 64 + lane]);
        float2 b = __ldg(&x2[(size_t)d * 64 + 32 + lane]);
        accA.x += a.x; accA.y += a.y; accB.x += b.x; accB.y += b.y;
    }

    out2[(size_t)warp_id * 64 + lane] = accA;
    out2[(size_t)warp_id * 64 + 32 + lane] = accB;
}

extern "C" void kernel_launch(void* const* d_in, const int* in_sizes, int n_in,
                              void* d_out, int out_size) {
    const float* x = (const float*)d_in[0];
    const int* edge_src = (const int*)d_in[1];
    const int* edge_dst = (const int*)d_in[2];
    float* out = (float*)d_out;
    int n_edges = in_sizes[1];

    // Kernel A: O(E) boundary-diff offsets
    {
        int threads = 256;
        int blocks = (n_edges + threads - 1) / threads;
        build_offsets_kernel<<<blocks, threads>>>(edge_src, n_edges);
    }

    // Kernel B: one warp per node, 4 warps per block
    {
        int threads = 128;
        int warps_per_block = threads / 32;
        int blocks = (N_NODES + warps_per_block - 1) / warps_per_block;
        graph_pool_kernel<<<blocks, threads>>>((const float2*)x, edge_dst,
                                               (float2*)out);
    }
}

// round 9
// speedup vs baseline: 1.0707x; 1.0707x over previous
#include <cuda_runtime.h>
#include <cuda_bf16.h>

#define N_NODES 50000
#define D_FEAT  128

// CSR row offsets into the sorted edge list. 50001 ints.
__device__ int g_offsets[N_NODES + 1];

// Kernel A: boundary-diff scatter, 4 edges per thread via int4.
// Thread handling edges [4t, 4t+4) fills offsets for all boundaries inside,
// using the previous element (edge_src[4t-1]) as the left neighbor.
__global__ void build_offsets_kernel(const int* __restrict__ edge_src, int n_edges) {
    int t = blockIdx.x * blockDim.x + threadIdx.x;
    int e0 = t * 4;
    if (e0 >= n_edges) return;
    int4 s = *reinterpret_cast<const int4*>(edge_src + e0);  // n_edges % 4 == 0
    int prev = (e0 == 0) ? -1 : edge_src[e0 - 1];
    // boundary before s.x
    for (int n = prev + 1; n <= s.x; n++) g_offsets[n] = e0;
    for (int n = s.x + 1; n <= s.y; n++) g_offsets[n] = e0 + 1;
    for (int n = s.y + 1; n <= s.z; n++) g_offsets[n] = e0 + 2;
    for (int n = s.z + 1; n <= s.w; n++) g_offsets[n] = e0 + 3;
    if (e0 + 4 >= n_edges) {
        for (int n = s.w + 1; n <= N_NODES; n++) g_offsets[n] = n_edges;
    }
}

// Kernel B: one warp per node, unroll-4 row gathers. Gathers use __ldcg
// (L2-only, no L1 allocation): random rows have ~1% L1 hit rate, so L1
// allocation is pure L1tex-pipe overhead; x stays L2-resident.
__global__ void __launch_bounds__(128)
graph_pool_kernel(const float4* __restrict__ x,
                  const int* __restrict__ edge_dst,
                  float4* __restrict__ out) {
    int warp_id = (blockIdx.x * blockDim.x + threadIdx.x) >> 5;
    int lane = threadIdx.x & 31;
    if (warp_id >= N_NODES) return;

    int beg = g_offsets[warp_id];
    int end = g_offsets[warp_id + 1];

    // self feature
    float4 acc = x[(size_t)warp_id * 32 + lane];

    int e = beg;
    for (; e + 4 <= end; e += 4) {
        int d0 = edge_dst[e + 0];
        int d1 = edge_dst[e + 1];
        int d2 = edge_dst[e + 2];
        int d3 = edge_dst[e + 3];
        float4 v0 = __ldcg(&x[(size_t)d0 * 32 + lane]);
        float4 v1 = __ldcg(&x[(size_t)d1 * 32 + lane]);
        float4 v2 = __ldcg(&x[(size_t)d2 * 32 + lane]);
        float4 v3 = __ldcg(&x[(size_t)d3 * 32 + lane]);
        acc.x += v0.x; acc.y += v0.y; acc.z += v0.z; acc.w += v0.w;
        acc.x += v1.x; acc.y += v1.y; acc.z += v1.z; acc.w += v1.w;
        acc.x += v2.x; acc.y += v2.y; acc.z += v2.z; acc.w += v2.w;
        acc.x += v3.x; acc.y += v3.y; acc.z += v3.z; acc.w += v3.w;
    }
    for (; e < end; e++) {
        int d = edge_dst[e];
        float4 v = __ldcg(&x[(size_t)d * 32 + lane]);
        acc.x += v.x; acc.y += v.y; acc.z += v.z; acc.w += v.w;
    }

    out[(size_t)warp_id * 32 + lane] = acc;
}

extern "C" void kernel_launch(void* const* d_in, const int* in_sizes, int n_in,
                              void* d_out, int out_size) {
    const float* x = (const float*)d_in[0];
    const int* edge_src = (const int*)d_in[1];
    const int* edge_dst = (const int*)d_in[2];
    float* out = (float*)d_out;
    int n_edges = in_sizes[1];

    // Kernel A: O(E) boundary-diff offsets, 4 edges/thread
    {
        int threads = 256;
        int work = (n_edges + 3) / 4;
        int blocks = (work + threads - 1) / threads;
        build_offsets_kernel<<<blocks, threads>>>(edge_src, n_edges);
    }

    // Kernel B: one warp per node, 4 warps per block
    {
        int threads = 128;
        int warps_per_block = threads / 32;
        int blocks = (N_NODES + warps_per_block - 1) / warps_per_block;
        graph_pool_kernel<<<blocks, threads>>>((const float4*)x, edge_dst,
                                               (float4*)out);
    }
}

// round 10
// speedup vs baseline: 1.0789x; 1.0077x over previous
#include <cuda_runtime.h>
#include <cuda_bf16.h>

#define N_NODES 50000
#define D_FEAT  128

// CSR row offsets into the sorted edge list. 50001 ints.
__device__ int g_offsets[N_NODES + 1];

// Kernel A: boundary-diff scatter, 4 edges per thread via int4.
__global__ void build_offsets_kernel(const int* __restrict__ edge_src, int n_edges) {
    int t = blockIdx.x * blockDim.x + threadIdx.x;
    int e0 = t * 4;
    if (e0 >= n_edges) return;
    int4 s = *reinterpret_cast<const int4*>(edge_src + e0);  // n_edges % 4 == 0
    int prev = (e0 == 0) ? -1 : edge_src[e0 - 1];
    for (int n = prev + 1; n <= s.x; n++) g_offsets[n] = e0;
    for (int n = s.x + 1; n <= s.y; n++) g_offsets[n] = e0 + 1;
    for (int n = s.y + 1; n <= s.z; n++) g_offsets[n] = e0 + 2;
    for (int n = s.z + 1; n <= s.w; n++) g_offsets[n] = e0 + 3;
    if (e0 + 4 >= n_edges) {
        for (int n = s.w + 1; n <= N_NODES; n++) g_offsets[n] = n_edges;
    }
}

// Kernel B: one warp per node, unroll-4 __ldcg row gathers (L2-direct),
// __stcg store (no L1 write-allocate), 2 warps per block for fine-grained
// scheduling and minimal block-retirement tail.
__global__ void __launch_bounds__(64)
graph_pool_kernel(const float4* __restrict__ x,
                  const int* __restrict__ edge_dst,
                  float4* __restrict__ out) {
    int warp_id = (blockIdx.x * blockDim.x + threadIdx.x) >> 5;
    int lane = threadIdx.x & 31;
    if (warp_id >= N_NODES) return;

    // issue range load first so its latency overlaps the self-row load
    int beg = g_offsets[warp_id];
    int end = g_offsets[warp_id + 1];

    float4 acc = x[(size_t)warp_id * 32 + lane];   // self feature

    int e = beg;
    for (; e + 4 <= end; e += 4) {
        int d0 = edge_dst[e + 0];
        int d1 = edge_dst[e + 1];
        int d2 = edge_dst[e + 2];
        int d3 = edge_dst[e + 3];
        float4 v0 = __ldcg(&x[(size_t)d0 * 32 + lane]);
        float4 v1 = __ldcg(&x[(size_t)d1 * 32 + lane]);
        float4 v2 = __ldcg(&x[(size_t)d2 * 32 + lane]);
        float4 v3 = __ldcg(&x[(size_t)d3 * 32 + lane]);
        acc.x += v0.x; acc.y += v0.y; acc.z += v0.z; acc.w += v0.w;
        acc.x += v1.x; acc.y += v1.y; acc.z += v1.z; acc.w += v1.w;
        acc.x += v2.x; acc.y += v2.y; acc.z += v2.z; acc.w += v2.w;
        acc.x += v3.x; acc.y += v3.y; acc.z += v3.z; acc.w += v3.w;
    }
    for (; e < end; e++) {
        int d = edge_dst[e];
        float4 v = __ldcg(&x[(size_t)d * 32 + lane]);
        acc.x += v.x; acc.y += v.y; acc.z += v.z; acc.w += v.w;
    }

    __stcg(&out[(size_t)warp_id * 32 + lane], acc);
}

extern "C" void kernel_launch(void* const* d_in, const int* in_sizes, int n_in,
                              void* d_out, int out_size) {
    const float* x = (const float*)d_in[0];
    const int* edge_src = (const int*)d_in[1];
    const int* edge_dst = (const int*)d_in[2];
    float* out = (float*)d_out;
    int n_edges = in_sizes[1];

    // Kernel A: O(E) boundary-diff offsets, 4 edges/thread
    {
        int threads = 256;
        int work = (n_edges + 3) / 4;
        int blocks = (work + threads - 1) / threads;
        build_offsets_kernel<<<blocks, threads>>>(edge_src, n_edges);
    }

    // Kernel B: one warp per node, 2 warps per block
    {
        int threads = 64;
        int warps_per_block = threads / 32;
        int blocks = (N_NODES + warps_per_block - 1) / warps_per_block;
        graph_pool_kernel<<<blocks, threads>>>((const float4*)x, edge_dst,
                                               (float4*)out);
    }
}

// round 11
// speedup vs baseline: 1.0801x; 1.0011x over previous
#include <cuda_runtime.h>
#include <cuda_bf16.h>

#define N_NODES 50000
#define D_FEAT  128

// CSR row offsets into the sorted edge list. 50001 ints.
__device__ int g_offsets[N_NODES + 1];

// Kernel A: boundary-diff scatter, 4 edges per thread via int4.
__global__ void build_offsets_kernel(const int* __restrict__ edge_src, int n_edges) {
    int t = blockIdx.x * blockDim.x + threadIdx.x;
    int e0 = t * 4;
    if (e0 >= n_edges) return;
    int4 s = *reinterpret_cast<const int4*>(edge_src + e0);  // n_edges % 4 == 0
    int prev = (e0 == 0) ? -1 : edge_src[e0 - 1];
    for (int n = prev + 1; n <= s.x; n++) g_offsets[n] = e0;
    for (int n = s.x + 1; n <= s.y; n++) g_offsets[n] = e0 + 1;
    for (int n = s.y + 1; n <= s.z; n++) g_offsets[n] = e0 + 2;
    for (int n = s.z + 1; n <= s.w; n++) g_offsets[n] = e0 + 3;
    if (e0 + 4 >= n_edges) {
        for (int n = s.w + 1; n <= N_NODES; n++) g_offsets[n] = n_edges;
    }
}

// Kernel B: one warp per node, unroll-4 __ldcg row gathers (L2-direct),
// __stcg store. Launched with PDL: the self-row load runs before
// cudaGridDependencySynchronize(), overlapping kernel A's tail + launch gap.
__global__ void __launch_bounds__(64)
graph_pool_kernel(const float4* __restrict__ x,
                  const int* __restrict__ edge_dst,
                  float4* __restrict__ out) {
    int warp_id = (blockIdx.x * blockDim.x + threadIdx.x) >> 5;
    int lane = threadIdx.x & 31;
    if (warp_id >= N_NODES) return;

    // Pre-dependency work: self feature row (independent of g_offsets).
    float4 acc = x[(size_t)warp_id * 32 + lane];

    // Gate on kernel A's completion (PDL).
    cudaGridDependencySynchronize();

    int beg = g_offsets[warp_id];
    int end = g_offsets[warp_id + 1];

    int e = beg;
    for (; e + 4 <= end; e += 4) {
        int d0 = edge_dst[e + 0];
        int d1 = edge_dst[e + 1];
        int d2 = edge_dst[e + 2];
        int d3 = edge_dst[e + 3];
        float4 v0 = __ldcg(&x[(size_t)d0 * 32 + lane]);
        float4 v1 = __ldcg(&x[(size_t)d1 * 32 + lane]);
        float4 v2 = __ldcg(&x[(size_t)d2 * 32 + lane]);
        float4 v3 = __ldcg(&x[(size_t)d3 * 32 + lane]);
        acc.x += v0.x; acc.y += v0.y; acc.z += v0.z; acc.w += v0.w;
        acc.x += v1.x; acc.y += v1.y; acc.z += v1.z; acc.w += v1.w;
        acc.x += v2.x; acc.y += v2.y; acc.z += v2.z; acc.w += v2.w;
        acc.x += v3.x; acc.y += v3.y; acc.z += v3.z; acc.w += v3.w;
    }
    for (; e < end; e++) {
        int d = edge_dst[e];
        float4 v = __ldcg(&x[(size_t)d * 32 + lane]);
        acc.x += v.x; acc.y += v.y; acc.z += v.z; acc.w += v.w;
    }

    __stcg(&out[(size_t)warp_id * 32 + lane], acc);
}

extern "C" void kernel_launch(void* const* d_in, const int* in_sizes, int n_in,
                              void* d_out, int out_size) {
    const float* x = (const float*)d_in[0];
    const int* edge_src = (const int*)d_in[1];
    const int* edge_dst = (const int*)d_in[2];
    float* out = (float*)d_out;
    int n_edges = in_sizes[1];

    // Kernel A: O(E) boundary-diff offsets, 4 edges/thread
    {
        int threads = 256;
        int work = (n_edges + 3) / 4;
        int blocks = (work + threads - 1) / threads;
        build_offsets_kernel<<<blocks, threads>>>(edge_src, n_edges);
    }

    // Kernel B: one warp per node, 2 warps per block, PDL overlap with A
    {
        int threads = 64;
        int warps_per_block = threads / 32;
        int blocks = (N_NODES + warps_per_block - 1) / warps_per_block;

        cudaLaunchConfig_t cfg = {};
        cfg.gridDim = dim3(blocks, 1, 1);
        cfg.blockDim = dim3(threads, 1, 1);
        cfg.dynamicSmemBytes = 0;
        cfg.stream = 0;  // legacy default stream (same as <<<>>> above)

        cudaLaunchAttribute attr[1];
        attr[0].id = cudaLaunchAttributeProgrammaticStreamSerialization;
        attr[0].val.programmaticStreamSerializationAllowed = 1;
        cfg.attrs = attr;
        cfg.numAttrs = 1;

        cudaLaunchKernelEx(&cfg, graph_pool_kernel,
                           (const float4*)x, edge_dst, (float4*)out);
    }
}